// round 4
// baseline (speedup 1.0000x reference)
#include <cuda_runtime.h>
#include <math.h>

// Problem constants
#define V_ 10000
#define E_ 512
#define H_ 512
#define L_ 2
#define S_ 128
#define B_ 128
#define M_ (S_*B_)     // 16384 rows for the step-parallel GEMMs
#define BH_ (B_*H_)    // 65536

// ---------------------------------------------------------------------------
// Device scratch (static __device__ globals; no allocation anywhere)
// ---------------------------------------------------------------------------
__device__ float g_X [(size_t)S_*B_*H_];   // pre-activations for current layer (32 MB)
__device__ float g_H1[(size_t)S_*B_*H_];   // layer-1 hidden states over time (32 MB)
__device__ float g_H2[(size_t)S_*B_*H_];   // layer-2 hidden states over time (32 MB)
__device__ float g_P [2][8*B_*H_];         // split-K partials, ping-pong (2x2 MB)
__device__ float g_Wt[L_*H_*H_];           // W_hh transposed per layer (2 MB)

// ---------------------------------------------------------------------------
// Transpose W_hh: g_Wt[l][k*H + j] = W_hh[l][j*H + k]
// ---------------------------------------------------------------------------
__global__ void transpose_whh_kernel(const float* __restrict__ Whh) {
    int idx = blockIdx.x * blockDim.x + threadIdx.x;    // over L*H*H
    int l = idx >> 18;                                   // H*H = 262144 = 2^18
    int r = idx & (H_*H_ - 1);
    int k = r >> 9;
    int j = r & (H_ - 1);
    g_Wt[idx] = __ldg(&Whh[l*H_*H_ + j*H_ + k]);
}

// ---------------------------------------------------------------------------
// Recurrence step kernel.
// Block (g, s): g = batch group of 8 (16 groups), s = k-slice of 64 (8 slices).
// Phase A: materialize h_{t-1}[g batches][64s..64s+64) by reducing the 8
//          split-K partials from the previous step (+ x + bias, tanh), store
//          to smem AND to H_out[t-1]. For t==0, h_{-1} = h0 (initial hidden).
// Phase B: compute new partial P_out[s][b][j] = sum_{k in slice} h*Wt[k][j]
//          for all 512 j, streaming Wt from L2 (float4 per thread).
// The kernel-launch boundary is the global barrier between steps.
// ---------------------------------------------------------------------------
__global__ __launch_bounds__(256) void rec_step_kernel(
    const float* __restrict__ x,      // [S][B][H] pre-activations for this layer
    const float* __restrict__ Wt,     // [H][H] transposed W_hh (this layer)
    const float* __restrict__ bias,   // [H]
    const float* __restrict__ h0,     // [B][H] initial hidden (this layer)
    const float* __restrict__ P_in,   // [8][B][H] partials from prev step
    float*       __restrict__ P_out,  // [8][B][H] partials for this step
    float*       __restrict__ H_out,  // [S][B][H] hidden states (this layer)
    int t)
{
    __shared__ float sh_h[8][64];
    const int tid = threadIdx.x;
    const int s = blockIdx.x & 7;
    const int g = blockIdx.x >> 3;

    // ---- Phase A: build h_{t-1} tile (8 batches x 64 hidden units) ----
    #pragma unroll
    for (int e = tid; e < 512; e += 256) {
        int bl = e >> 6, jj = e & 63;
        int b = g*8 + bl;
        int j = s*64 + jj;
        float v;
        if (t == 0) {
            v = h0[b*H_ + j];
        } else {
            int off = b*H_ + j;
            v = x[(size_t)(t-1)*BH_ + off] + bias[j];
            #pragma unroll
            for (int sp = 0; sp < 8; sp++) v += P_in[sp*BH_ + off];
            v = tanhf(v);
            H_out[(size_t)(t-1)*BH_ + off] = v;
        }
        sh_h[bl][jj] = v;
    }
    __syncthreads();

    // ---- Phase B: partial matmul over this k-slice ----
    const int tj = tid & 127;     // 128 j-threads, 4 cols each -> 512 cols
    const int tb = tid >> 7;      // 2 batch sub-groups of 4
    const int j4 = tj * 4;

    float acc[4][4];
    #pragma unroll
    for (int i = 0; i < 4; i++)
        #pragma unroll
        for (int q = 0; q < 4; q++) acc[i][q] = 0.f;

    const float4* wptr = (const float4*)(Wt + (size_t)(s*64)*H_ + j4);
    #pragma unroll 8
    for (int k = 0; k < 64; k++) {
        float4 w = wptr[k * (H_/4)];
        #pragma unroll
        for (int bb = 0; bb < 4; bb++) {
            float hv = sh_h[tb*4 + bb][k];
            acc[bb][0] += hv * w.x;
            acc[bb][1] += hv * w.y;
            acc[bb][2] += hv * w.z;
            acc[bb][3] += hv * w.w;
        }
    }

    #pragma unroll
    for (int bb = 0; bb < 4; bb++) {
        int b = g*8 + tb*4 + bb;
        float4 o = make_float4(acc[bb][0], acc[bb][1], acc[bb][2], acc[bb][3]);
        *(float4*)(P_out + (size_t)s*BH_ + b*H_ + j4) = o;
    }
}

// ---------------------------------------------------------------------------
// Recurrence epilogue: materialize h_{S-1}, store to H_out[S-1] and to the
// h_final section of d_out.
// ---------------------------------------------------------------------------
__global__ void rec_final_kernel(
    const float* __restrict__ x,
    const float* __restrict__ bias,
    const float* __restrict__ P_in,
    float*       __restrict__ H_out,
    float*       __restrict__ hfinal)
{
    int idx = blockIdx.x * blockDim.x + threadIdx.x;   // < B*H
    int j = idx & (H_ - 1);
    float v = x[(size_t)(S_-1)*BH_ + idx] + bias[j];
    #pragma unroll
    for (int sp = 0; sp < 8; sp++) v += P_in[sp*BH_ + idx];
    v = tanhf(v);
    H_out[(size_t)(S_-1)*BH_ + idx] = v;
    hfinal[idx] = v;
}

// ---------------------------------------------------------------------------
// fp32 SGEMM: C[m][n] = sum_k A[row(m)][k] * Bm[n][k] (+ bias[n])
//   A: [*, K] row-major; row(m) = gather ? gather[m] : m
//   Bm: [N, K] row-major (so this is A @ Bm^T)
// BM=BN=128, BK=8, 256 threads, 8x8 micro-tile, register prefetch.
// M must be a multiple of 128 (true: 16384). N handled with bounds
// (N = 512 or 10000; both divisible by 4, so float4 stores are safe).
// ---------------------------------------------------------------------------
__global__ __launch_bounds__(256) void sgemm_kernel(
    const float* __restrict__ A,
    const int*   __restrict__ gather,
    const float* __restrict__ Bm,
    const float* __restrict__ bias,
    float*       __restrict__ C,
    int N, int K)
{
    __shared__ float As[8][128];
    __shared__ float Bs[8][128];

    const int tid = threadIdx.x;
    const int bm = blockIdx.y * 128;
    const int bn = blockIdx.x * 128;

    const int lrow = tid >> 1;
    const int lcol = (tid & 1) * 4;

    int am = bm + lrow;
    int arow = gather ? gather[am] : am;
    const float* Ap = A + (size_t)arow * K + lcol;

    int nrow = bn + lrow;
    if (nrow >= N) nrow = N - 1;                 // clamp (excluded at store)
    const float* Bp = Bm + (size_t)nrow * K + lcol;

    float4 areg = *(const float4*)Ap;
    float4 breg = *(const float4*)Bp;

    const int tx = tid & 15, ty = tid >> 4;
    float acc[8][8];
    #pragma unroll
    for (int i = 0; i < 8; i++)
        #pragma unroll
        for (int q = 0; q < 8; q++) acc[i][q] = 0.f;

    for (int kt = 0; kt < K; kt += 8) {
        As[lcol+0][lrow] = areg.x; As[lcol+1][lrow] = areg.y;
        As[lcol+2][lrow] = areg.z; As[lcol+3][lrow] = areg.w;
        Bs[lcol+0][lrow] = breg.x; Bs[lcol+1][lrow] = breg.y;
        Bs[lcol+2][lrow] = breg.z; Bs[lcol+3][lrow] = breg.w;
        __syncthreads();

        if (kt + 8 < K) {
            areg = *(const float4*)(Ap + kt + 8);
            breg = *(const float4*)(Bp + kt + 8);
        }

        #pragma unroll
        for (int kk = 0; kk < 8; kk++) {
            float a[8], b[8];
            *(float4*)(a)     = *(const float4*)&As[kk][ty*8];
            *(float4*)(a + 4) = *(const float4*)&As[kk][ty*8 + 4];
            *(float4*)(b)     = *(const float4*)&Bs[kk][tx*8];
            *(float4*)(b + 4) = *(const float4*)&Bs[kk][tx*8 + 4];
            #pragma unroll
            for (int i = 0; i < 8; i++)
                #pragma unroll
                for (int q = 0; q < 8; q++)
                    acc[i][q] += a[i] * b[q];
        }
        __syncthreads();
    }

    const int cn = bn + tx * 8;
    float bi[8];
    #pragma unroll
    for (int q = 0; q < 8; q++)
        bi[q] = (bias != nullptr && (cn + q) < N) ? bias[cn + q] : 0.f;

    #pragma unroll
    for (int i = 0; i < 8; i++) {
        int row = bm + ty*8 + i;
        float* crow = C + (size_t)row * N;
        float4 v0 = make_float4(acc[i][0]+bi[0], acc[i][1]+bi[1],
                                acc[i][2]+bi[2], acc[i][3]+bi[3]);
        float4 v1 = make_float4(acc[i][4]+bi[4], acc[i][5]+bi[5],
                                acc[i][6]+bi[6], acc[i][7]+bi[7]);
        if (cn + 3 < N) *(float4*)(crow + cn)     = v0;
        if (cn + 7 < N) *(float4*)(crow + cn + 4) = v1;
    }
}

// ---------------------------------------------------------------------------
// Launch: all kernel launches on the capture stream (default <<<>>>).
// ---------------------------------------------------------------------------
extern "C" void kernel_launch(void* const* d_in, const int* in_sizes, int n_in,
                              void* d_out, int out_size)
{
    (void)in_sizes; (void)n_in; (void)out_size;

    const int*   inputs = (const int*)  d_in[0];  // [S, B]
    const float* hidden = (const float*)d_in[1];  // [L, B, H]
    const float* emb    = (const float*)d_in[2];  // [V, E]
    const float* W_ih   = (const float*)d_in[3];  // [L, H, H]
    const float* W_hh   = (const float*)d_in[4];  // [L, H, H]
    const float* b_hh   = (const float*)d_in[5];  // [L, H]
    const float* W_out  = (const float*)d_in[6];  // [V, H]
    const float* b_out  = (const float*)d_in[7];  // [V]
    float* out = (float*)d_out;                   // logits [S,B,V] then h_final [L,B,H]

    float *X, *H1, *H2, *P, *Wt;
    cudaGetSymbolAddress((void**)&X,  g_X);
    cudaGetSymbolAddress((void**)&H1, g_H1);
    cudaGetSymbolAddress((void**)&H2, g_H2);
    cudaGetSymbolAddress((void**)&P,  g_P);
    cudaGetSymbolAddress((void**)&Wt, g_Wt);
    float* P0 = P;
    float* P1 = P + 8*BH_;

    float* hfinal0 = out + (size_t)S_*B_*V_;
    float* hfinal1 = hfinal0 + BH_;

    // 0) transpose W_hh for both layers
    transpose_whh_kernel<<<(L_*H_*H_)/256, 256>>>(W_hh);

    // 1) X0 = emb[tok] @ W_ih0^T   (M=16384, N=512, K=512, gathered A)
    {
        dim3 grid(H_/128, M_/128);
        sgemm_kernel<<<grid, 256>>>(emb, inputs, W_ih, nullptr, X, H_, H_);
    }

    // 2) recurrence layer 1 -> H1
    for (int t = 0; t < S_; t++) {
        const float* pin  = (t & 1) ? P0 : P1;
        float*       pout = (t & 1) ? P1 : P0;
        rec_step_kernel<<<128, 256>>>(X, Wt, b_hh, hidden, pin, pout, H1, t);
    }
    rec_final_kernel<<<BH_/256, 256>>>(X, b_hh, P1, H1, hfinal0);

    // 3) X1 = H1 @ W_ih1^T
    {
        dim3 grid(H_/128, M_/128);
        sgemm_kernel<<<grid, 256>>>(H1, nullptr, W_ih + H_*H_, nullptr, X, H_, H_);
    }

    // 4) recurrence layer 2 -> H2
    for (int t = 0; t < S_; t++) {
        const float* pin  = (t & 1) ? P0 : P1;
        float*       pout = (t & 1) ? P1 : P0;
        rec_step_kernel<<<128, 256>>>(X, Wt + H_*H_, b_hh + H_, hidden + BH_,
                                      pin, pout, H2, t);
    }
    rec_final_kernel<<<BH_/256, 256>>>(X, b_hh + H_, P1, H2, hfinal1);

    // 5) logits = H2 @ W_out^T + b_out   (M=16384, N=10000, K=512)
    {
        dim3 grid((V_ + 127)/128, M_/128);
        sgemm_kernel<<<grid, 256>>>(H2, nullptr, W_out, b_out, out, V_, H_);
    }
}

// round 5
// speedup vs baseline: 1.0016x; 1.0016x over previous
#include <cuda_runtime.h>
#include <math.h>

// Problem constants
#define V_ 10000
#define E_ 512
#define H_ 512
#define L_ 2
#define S_ 128
#define B_ 128
#define M_ (S_*B_)     // 16384 rows for the step-parallel GEMMs
#define BH_ (B_*H_)    // 65536

// ---------------------------------------------------------------------------
// Device scratch (static __device__ globals; no allocation anywhere)
// ---------------------------------------------------------------------------
__device__ float g_X [(size_t)S_*B_*H_];   // pre-activations for current layer (32 MB)
__device__ float g_H1[(size_t)S_*B_*H_];   // layer-1 hidden states over time (32 MB)
__device__ float g_H2[(size_t)S_*B_*H_];   // layer-2 hidden states over time (32 MB)
__device__ float g_P [2][8*B_*H_];         // split-K partials, ping-pong (2x2 MB)
__device__ float g_Wt[L_*H_*H_];           // W_hh transposed per layer (2 MB)

// ---------------------------------------------------------------------------
// Transpose W_hh: g_Wt[l][k*H + j] = W_hh[l][j*H + k]
// ---------------------------------------------------------------------------
__global__ void transpose_whh_kernel(const float* __restrict__ Whh) {
    int idx = blockIdx.x * blockDim.x + threadIdx.x;    // over L*H*H
    int l = idx >> 18;                                   // H*H = 262144 = 2^18
    int r = idx & (H_*H_ - 1);
    int k = r >> 9;
    int j = r & (H_ - 1);
    g_Wt[idx] = __ldg(&Whh[l*H_*H_ + j*H_ + k]);
}

// ---------------------------------------------------------------------------
// Recurrence step kernel.
// Block (g, s): g = batch group of 8 (16 groups), s = k-slice of 64 (8 slices).
// Phase A: materialize h_{t-1}[g batches][64s..64s+64) by reducing the 8
//          split-K partials from the previous step (+ x + bias, tanh), store
//          to smem AND to H_out[t-1]. For t==0, h_{-1} = h0 (initial hidden).
// Phase B: compute new partial P_out[s][b][j] = sum_{k in slice} h*Wt[k][j]
//          for all 512 j, streaming Wt from L2 (float4 per thread).
// The kernel-launch boundary is the global barrier between steps.
// ---------------------------------------------------------------------------
__global__ __launch_bounds__(256) void rec_step_kernel(
    const float* __restrict__ x,      // [S][B][H] pre-activations for this layer
    const float* __restrict__ Wt,     // [H][H] transposed W_hh (this layer)
    const float* __restrict__ bias,   // [H]
    const float* __restrict__ h0,     // [B][H] initial hidden (this layer)
    const float* __restrict__ P_in,   // [8][B][H] partials from prev step
    float*       __restrict__ P_out,  // [8][B][H] partials for this step
    float*       __restrict__ H_out,  // [S][B][H] hidden states (this layer)
    int t)
{
    __shared__ float sh_h[8][64];
    const int tid = threadIdx.x;
    const int s = blockIdx.x & 7;
    const int g = blockIdx.x >> 3;

    // ---- Phase A: build h_{t-1} tile (8 batches x 64 hidden units) ----
    #pragma unroll
    for (int e = tid; e < 512; e += 256) {
        int bl = e >> 6, jj = e & 63;
        int b = g*8 + bl;
        int j = s*64 + jj;
        float v;
        if (t == 0) {
            v = h0[b*H_ + j];
        } else {
            int off = b*H_ + j;
            v = x[(size_t)(t-1)*BH_ + off] + bias[j];
            #pragma unroll
            for (int sp = 0; sp < 8; sp++) v += P_in[sp*BH_ + off];
            v = tanhf(v);
            H_out[(size_t)(t-1)*BH_ + off] = v;
        }
        sh_h[bl][jj] = v;
    }
    __syncthreads();

    // ---- Phase B: partial matmul over this k-slice ----
    const int tj = tid & 127;     // 128 j-threads, 4 cols each -> 512 cols
    const int tb = tid >> 7;      // 2 batch sub-groups of 4
    const int j4 = tj * 4;

    float acc[4][4];
    #pragma unroll
    for (int i = 0; i < 4; i++)
        #pragma unroll
        for (int q = 0; q < 4; q++) acc[i][q] = 0.f;

    const float4* wptr = (const float4*)(Wt + (size_t)(s*64)*H_ + j4);
    #pragma unroll 8
    for (int k = 0; k < 64; k++) {
        float4 w = wptr[k * (H_/4)];
        #pragma unroll
        for (int bb = 0; bb < 4; bb++) {
            float hv = sh_h[tb*4 + bb][k];
            acc[bb][0] += hv * w.x;
            acc[bb][1] += hv * w.y;
            acc[bb][2] += hv * w.z;
            acc[bb][3] += hv * w.w;
        }
    }

    #pragma unroll
    for (int bb = 0; bb < 4; bb++) {
        int b = g*8 + tb*4 + bb;
        float4 o = make_float4(acc[bb][0], acc[bb][1], acc[bb][2], acc[bb][3]);
        *(float4*)(P_out + (size_t)s*BH_ + b*H_ + j4) = o;
    }
}

// ---------------------------------------------------------------------------
// Recurrence epilogue: materialize h_{S-1}, store to H_out[S-1] and to the
// h_final section of d_out.
// ---------------------------------------------------------------------------
__global__ void rec_final_kernel(
    const float* __restrict__ x,
    const float* __restrict__ bias,
    const float* __restrict__ P_in,
    float*       __restrict__ H_out,
    float*       __restrict__ hfinal)
{
    int idx = blockIdx.x * blockDim.x + threadIdx.x;   // < B*H
    int j = idx & (H_ - 1);
    float v = x[(size_t)(S_-1)*BH_ + idx] + bias[j];
    #pragma unroll
    for (int sp = 0; sp < 8; sp++) v += P_in[sp*BH_ + idx];
    v = tanhf(v);
    H_out[(size_t)(S_-1)*BH_ + idx] = v;
    hfinal[idx] = v;
}

// ---------------------------------------------------------------------------
// fp32 SGEMM: C[m][n] = sum_k A[row(m)][k] * Bm[n][k] (+ bias[n])
//   A: [*, K] row-major; row(m) = gather ? gather[m] : m
//   Bm: [N, K] row-major (so this is A @ Bm^T)
// BM=BN=128, BK=8, 256 threads, 8x8 micro-tile, register prefetch.
// M must be a multiple of 128 (true: 16384). N handled with bounds
// (N = 512 or 10000; both divisible by 4, so float4 stores are safe).
// ---------------------------------------------------------------------------
__global__ __launch_bounds__(256) void sgemm_kernel(
    const float* __restrict__ A,
    const int*   __restrict__ gather,
    const float* __restrict__ Bm,
    const float* __restrict__ bias,
    float*       __restrict__ C,
    int N, int K)
{
    __shared__ float As[8][128];
    __shared__ float Bs[8][128];

    const int tid = threadIdx.x;
    const int bm = blockIdx.y * 128;
    const int bn = blockIdx.x * 128;

    const int lrow = tid >> 1;
    const int lcol = (tid & 1) * 4;

    int am = bm + lrow;
    int arow = gather ? gather[am] : am;
    const float* Ap = A + (size_t)arow * K + lcol;

    int nrow = bn + lrow;
    if (nrow >= N) nrow = N - 1;                 // clamp (excluded at store)
    const float* Bp = Bm + (size_t)nrow * K + lcol;

    float4 areg = *(const float4*)Ap;
    float4 breg = *(const float4*)Bp;

    const int tx = tid & 15, ty = tid >> 4;
    float acc[8][8];
    #pragma unroll
    for (int i = 0; i < 8; i++)
        #pragma unroll
        for (int q = 0; q < 8; q++) acc[i][q] = 0.f;

    for (int kt = 0; kt < K; kt += 8) {
        As[lcol+0][lrow] = areg.x; As[lcol+1][lrow] = areg.y;
        As[lcol+2][lrow] = areg.z; As[lcol+3][lrow] = areg.w;
        Bs[lcol+0][lrow] = breg.x; Bs[lcol+1][lrow] = breg.y;
        Bs[lcol+2][lrow] = breg.z; Bs[lcol+3][lrow] = breg.w;
        __syncthreads();

        if (kt + 8 < K) {
            areg = *(const float4*)(Ap + kt + 8);
            breg = *(const float4*)(Bp + kt + 8);
        }

        #pragma unroll
        for (int kk = 0; kk < 8; kk++) {
            float a[8], b[8];
            *(float4*)(a)     = *(const float4*)&As[kk][ty*8];
            *(float4*)(a + 4) = *(const float4*)&As[kk][ty*8 + 4];
            *(float4*)(b)     = *(const float4*)&Bs[kk][tx*8];
            *(float4*)(b + 4) = *(const float4*)&Bs[kk][tx*8 + 4];
            #pragma unroll
            for (int i = 0; i < 8; i++)
                #pragma unroll
                for (int q = 0; q < 8; q++)
                    acc[i][q] += a[i] * b[q];
        }
        __syncthreads();
    }

    const int cn = bn + tx * 8;
    float bi[8];
    #pragma unroll
    for (int q = 0; q < 8; q++)
        bi[q] = (bias != nullptr && (cn + q) < N) ? bias[cn + q] : 0.f;

    #pragma unroll
    for (int i = 0; i < 8; i++) {
        int row = bm + ty*8 + i;
        float* crow = C + (size_t)row * N;
        float4 v0 = make_float4(acc[i][0]+bi[0], acc[i][1]+bi[1],
                                acc[i][2]+bi[2], acc[i][3]+bi[3]);
        float4 v1 = make_float4(acc[i][4]+bi[4], acc[i][5]+bi[5],
                                acc[i][6]+bi[6], acc[i][7]+bi[7]);
        if (cn + 3 < N) *(float4*)(crow + cn)     = v0;
        if (cn + 7 < N) *(float4*)(crow + cn + 4) = v1;
    }
}

// ---------------------------------------------------------------------------
// Launch: all kernel launches on the capture stream (default <<<>>>).
// ---------------------------------------------------------------------------
extern "C" void kernel_launch(void* const* d_in, const int* in_sizes, int n_in,
                              void* d_out, int out_size)
{
    (void)in_sizes; (void)n_in; (void)out_size;

    const int*   inputs = (const int*)  d_in[0];  // [S, B]
    const float* hidden = (const float*)d_in[1];  // [L, B, H]
    const float* emb    = (const float*)d_in[2];  // [V, E]
    const float* W_ih   = (const float*)d_in[3];  // [L, H, H]
    const float* W_hh   = (const float*)d_in[4];  // [L, H, H]
    const float* b_hh   = (const float*)d_in[5];  // [L, H]
    const float* W_out  = (const float*)d_in[6];  // [V, H]
    const float* b_out  = (const float*)d_in[7];  // [V]
    float* out = (float*)d_out;                   // logits [S,B,V] then h_final [L,B,H]

    float *X, *H1, *H2, *P, *Wt;
    cudaGetSymbolAddress((void**)&X,  g_X);
    cudaGetSymbolAddress((void**)&H1, g_H1);
    cudaGetSymbolAddress((void**)&H2, g_H2);
    cudaGetSymbolAddress((void**)&P,  g_P);
    cudaGetSymbolAddress((void**)&Wt, g_Wt);
    float* P0 = P;
    float* P1 = P + 8*BH_;

    float* hfinal0 = out + (size_t)S_*B_*V_;
    float* hfinal1 = hfinal0 + BH_;

    // 0) transpose W_hh for both layers
    transpose_whh_kernel<<<(L_*H_*H_)/256, 256>>>(W_hh);

    // 1) X0 = emb[tok] @ W_ih0^T   (M=16384, N=512, K=512, gathered A)
    {
        dim3 grid(H_/128, M_/128);
        sgemm_kernel<<<grid, 256>>>(emb, inputs, W_ih, nullptr, X, H_, H_);
    }

    // 2) recurrence layer 1 -> H1
    for (int t = 0; t < S_; t++) {
        const float* pin  = (t & 1) ? P0 : P1;
        float*       pout = (t & 1) ? P1 : P0;
        rec_step_kernel<<<128, 256>>>(X, Wt, b_hh, hidden, pin, pout, H1, t);
    }
    rec_final_kernel<<<BH_/256, 256>>>(X, b_hh, P1, H1, hfinal0);

    // 3) X1 = H1 @ W_ih1^T
    {
        dim3 grid(H_/128, M_/128);
        sgemm_kernel<<<grid, 256>>>(H1, nullptr, W_ih + H_*H_, nullptr, X, H_, H_);
    }

    // 4) recurrence layer 2 -> H2
    for (int t = 0; t < S_; t++) {
        const float* pin  = (t & 1) ? P0 : P1;
        float*       pout = (t & 1) ? P1 : P0;
        rec_step_kernel<<<128, 256>>>(X, Wt + H_*H_, b_hh + H_, hidden + BH_,
                                      pin, pout, H2, t);
    }
    rec_final_kernel<<<BH_/256, 256>>>(X, b_hh + H_, P1, H2, hfinal1);

    // 5) logits = H2 @ W_out^T + b_out   (M=16384, N=10000, K=512)
    {
        dim3 grid((V_ + 127)/128, M_/128);
        sgemm_kernel<<<grid, 256>>>(H2, nullptr, W_out, b_out, out, V_, H_);
    }
}